// round 1
// baseline (speedup 1.0000x reference)
#include <cuda_runtime.h>
#include <cuda_bf16.h>
#include <math.h>

// Problem dims (fixed by the dataset)
#define B_ 32
#define T_ 512
#define D_ 1024
#define H_ 1024
#define ZN 4096            // 4*H
#define NBLK 128           // persistent blocks (<= SM count 152, all resident)

// ---------------- device scratch (allocation-guard-safe) ----------------
__device__ float g_G[(size_t)T_ * B_ * ZN];   // 256 MB: precomputed x@Wx + bias, t-major, reversed time
__device__ float g_h[2][H_ * B_];             // double-buffered hidden state, layout [n][b] (k-major for GEMM)
__device__ unsigned g_bar = 0;                // grid barrier arrival counter
__device__ unsigned g_done = 0;               // exit/reset counter

// ---------------- helpers ----------------
__device__ __forceinline__ float sigf(float x) { return 1.0f / (1.0f + __expf(-x)); }

// ---------------- Phase 1: G = x_reversed @ Wx + bias ----------------
// C[M=16384, N=4096] with K=1024. Row r = t*32+b maps to x[b, T-1-t, :].
__global__ __launch_bounds__(256) void gemm_xw(const float* __restrict__ x,
                                               const float* __restrict__ W,
                                               const float* __restrict__ bias) {
    __shared__ float As[16][64];   // [k][m]
    __shared__ float Bs[16][64];   // [k][n]
    const int tid = threadIdx.x;
    const int bn = blockIdx.x;     // N tile (64 cols)
    const int bm = blockIdx.y;     // M tile (64 rows)
    const int tr = tid >> 4;       // 0..15  (m micro-row)
    const int tc = tid & 15;       // 0..15  (n micro-col)

    // A staging: thread loads float4 along K for one m-row
    const int mA  = tid >> 2;          // 0..63
    const int kqA = (tid & 3) * 4;     // 0,4,8,12
    const int rowA = bm * 64 + mA;
    const int tA = rowA >> 5;
    const int bA = rowA & 31;
    const float* arow = x + ((size_t)bA * T_ + (size_t)(T_ - 1 - tA)) * D_;

    // B staging: thread loads float4 along N for one k-row
    const int kB  = tid >> 4;          // 0..15
    const int nqB = (tid & 15) * 4;    // 0..60

    float acc[4][4] = {};

    for (int kc = 0; kc < D_; kc += 16) {
        float4 av = *(const float4*)(arow + kc + kqA);
        As[kqA + 0][mA] = av.x;
        As[kqA + 1][mA] = av.y;
        As[kqA + 2][mA] = av.z;
        As[kqA + 3][mA] = av.w;
        float4 bv = *(const float4*)(W + (size_t)(kc + kB) * ZN + bn * 64 + nqB);
        *(float4*)&Bs[kB][nqB] = bv;
        __syncthreads();
#pragma unroll
        for (int k = 0; k < 16; ++k) {
            float4 a4 = *(const float4*)&As[k][tr * 4];
            float4 b4 = *(const float4*)&Bs[k][tc * 4];
            acc[0][0] += a4.x * b4.x; acc[0][1] += a4.x * b4.y; acc[0][2] += a4.x * b4.z; acc[0][3] += a4.x * b4.w;
            acc[1][0] += a4.y * b4.x; acc[1][1] += a4.y * b4.y; acc[1][2] += a4.y * b4.z; acc[1][3] += a4.y * b4.w;
            acc[2][0] += a4.z * b4.x; acc[2][1] += a4.z * b4.y; acc[2][2] += a4.z * b4.z; acc[2][3] += a4.z * b4.w;
            acc[3][0] += a4.w * b4.x; acc[3][1] += a4.w * b4.y; acc[3][2] += a4.w * b4.z; acc[3][3] += a4.w * b4.w;
        }
        __syncthreads();
    }

    float4 bb = *(const float4*)(bias + bn * 64 + tc * 4);
#pragma unroll
    for (int i = 0; i < 4; ++i) {
        int row = bm * 64 + tr * 4 + i;
        float4 v;
        v.x = acc[i][0] + bb.x;
        v.y = acc[i][1] + bb.y;
        v.z = acc[i][2] + bb.z;
        v.w = acc[i][3] + bb.w;
        *(float4*)&g_G[(size_t)row * ZN + bn * 64 + tc * 4] = v;
    }
}

// ---------------- grid barrier ----------------
__device__ __forceinline__ void grid_sync(unsigned epoch) {
    __syncthreads();
    if (threadIdx.x == 0) {
        __threadfence();
        atomicAdd(&g_bar, 1u);
        const unsigned target = epoch * NBLK;
        while (atomicAdd(&g_bar, 0u) < target) { }
    }
    __syncthreads();
}

// ---------------- Phase 2: persistent sequential LSTM ----------------
// Each block owns 8 hidden columns (n0..n0+7) -> a 32x32 z-tile (4 gates x 8 cols).
// h is double-buffered in g_h with layout [n][b] so k-chunks load coalesced.
__global__ __launch_bounds__(256) void lstm_seq(const float* __restrict__ Wfull,
                                                float* __restrict__ out) {
    const float* Wh = Wfull + (size_t)D_ * ZN;   // recurrent weight rows

    __shared__ float h_s[64][32];     // [k][b]
    __shared__ float w_s[64][32];     // [k][c], c = gate*8 + dn
    __shared__ float z_s[32][33];     // z tile, padded

    const int tid = threadIdx.x;
    const int n0  = blockIdx.x * 8;
    const int tr  = tid & 15;         // row-pair index (rows 2tr, 2tr+1)
    const int tc  = tid >> 4;         // col-pair index (cols 2tc, 2tc+1)
    const int pb  = tid >> 3;         // pointwise: batch row 0..31
    const int pn  = tid & 7;          // pointwise: local hidden col 0..7

    const int c0 = 2 * tc, c1 = 2 * tc + 1;
    const int zcol0 = (c0 >> 3) * 1024 + n0 + (c0 & 7);
    const int zcol1 = (c1 >> 3) * 1024 + n0 + (c1 & 7);
    const int r0 = 2 * tr, r1 = 2 * tr + 1;

    float c_reg = 0.0f;

    // ---- step 0: h = 0, z = G[0] ----
    {
        const float* G0 = g_G;
        float iv = G0[(size_t)pb * ZN + 0 * 1024 + n0 + pn];
        float jv = G0[(size_t)pb * ZN + 1 * 1024 + n0 + pn];
        float fv = G0[(size_t)pb * ZN + 2 * 1024 + n0 + pn];
        float ov = G0[(size_t)pb * ZN + 3 * 1024 + n0 + pn];
        c_reg = sigf(fv + 1.0f) * 0.0f + sigf(iv) * tanhf(jv);
        float hv = sigf(ov) * tanhf(c_reg);
        out[(size_t)pb * (T_ * H_) + 0 * H_ + n0 + pn] = c_reg;
        __stcg(&g_h[1][(n0 + pn) * 32 + pb], hv);
    }

    for (int t = 1; t < T_; ++t) {
        grid_sync((unsigned)t);       // all h writes of step t-1 visible
        const int buf = t & 1;        // buffer written at step t-1
        const float* Gt = g_G + (size_t)t * (B_ * ZN);

        float acc00 = Gt[(size_t)r0 * ZN + zcol0];
        float acc01 = Gt[(size_t)r0 * ZN + zcol1];
        float acc10 = Gt[(size_t)r1 * ZN + zcol0];
        float acc11 = Gt[(size_t)r1 * ZN + zcol1];

        for (int kc = 0; kc < H_; kc += 64) {
#pragma unroll
            for (int i = 0; i < 8; ++i) {
                int idx = tid + i * 256;          // 0..2047
                int kk = idx >> 5;
                int cc = idx & 31;
                h_s[kk][cc] = __ldcg(&g_h[buf][(kc + kk) * 32 + cc]);
                w_s[kk][cc] = __ldg(&Wh[(size_t)(kc + kk) * ZN + (cc >> 3) * 1024 + n0 + (cc & 7)]);
            }
            __syncthreads();
#pragma unroll 16
            for (int k = 0; k < 64; ++k) {
                float2 hh = *(const float2*)&h_s[k][2 * tr];
                float2 ww = *(const float2*)&w_s[k][2 * tc];
                acc00 += hh.x * ww.x; acc01 += hh.x * ww.y;
                acc10 += hh.y * ww.x; acc11 += hh.y * ww.y;
            }
            __syncthreads();
        }

        z_s[r0][c0] = acc00; z_s[r0][c1] = acc01;
        z_s[r1][c0] = acc10; z_s[r1][c1] = acc11;
        __syncthreads();

        float iv = z_s[pb][pn];
        float jv = z_s[pb][8 + pn];
        float fv = z_s[pb][16 + pn];
        float ov = z_s[pb][24 + pn];
        c_reg = sigf(fv + 1.0f) * c_reg + sigf(iv) * tanhf(jv);
        float hv = sigf(ov) * tanhf(c_reg);
        out[(size_t)pb * (T_ * H_) + (size_t)t * H_ + n0 + pn] = c_reg;
        __stcg(&g_h[(t + 1) & 1][(n0 + pn) * 32 + pb], hv);
        // next grid_sync provides the block-level sync before z_s/h_s reuse
        __syncthreads();
    }

    // ---- reset barrier counters for deterministic graph replay ----
    __syncthreads();
    if (tid == 0) {
        __threadfence();
        atomicAdd(&g_done, 1u);
        if (blockIdx.x == 0) {
            while (atomicAdd(&g_done, 0u) < (unsigned)NBLK) { }
            g_bar = 0u;
            __threadfence();
            g_done = 0u;
            __threadfence();
        }
    }
}

// ---------------- launch ----------------
extern "C" void kernel_launch(void* const* d_in, const int* in_sizes, int n_in,
                              void* d_out, int out_size) {
    (void)in_sizes; (void)n_in; (void)out_size;
    const float* x    = (const float*)d_in[0];
    // d_in[1] = sl (int32) — unused by the reference computation
    const float* kern = (const float*)d_in[2];
    const float* bias = (const float*)d_in[3];
    float* out = (float*)d_out;

    dim3 g1(ZN / 64, (B_ * T_) / 64);   // (64, 256)
    gemm_xw<<<g1, 256>>>(x, kern, bias);
    lstm_seq<<<NBLK, 256>>>(kern, out);
}

// round 2
// speedup vs baseline: 2.8744x; 2.8744x over previous
#include <cuda_runtime.h>
#include <cuda_bf16.h>
#include <math.h>
#include <stdint.h>

#define B_ 32
#define T_ 512
#define D_ 1024
#define H_ 1024
#define ZN 4096
#define NBLK 128

// ---------------- device scratch ----------------
__device__ float g_G[(size_t)T_ * B_ * ZN];   // 256MB: x@Wx + bias, row r = t*32+b (reversed time)
__device__ float g_h[2][H_ * B_];             // double-buffered h, layout [k][b], tf32-rounded
__device__ unsigned g_bar = 0;
__device__ unsigned g_done = 0;

// ---------------- helpers ----------------
__device__ __forceinline__ float sigf(float x) { return 1.0f / (1.0f + __expf(-x)); }

__device__ __forceinline__ uint32_t f2tf32(float x) {
    uint32_t u;
    asm("cvt.rna.tf32.f32 %0, %1;" : "=r"(u) : "f"(x));
    return u;
}

__device__ __forceinline__ void mma_m16n8k8(float* c, const uint32_t* a, const uint32_t* b) {
    asm volatile(
        "mma.sync.aligned.m16n8k8.row.col.f32.tf32.tf32.f32 "
        "{%0,%1,%2,%3}, {%4,%5,%6,%7}, {%8,%9}, {%0,%1,%2,%3};"
        : "+f"(c[0]), "+f"(c[1]), "+f"(c[2]), "+f"(c[3])
        : "r"(a[0]), "r"(a[1]), "r"(a[2]), "r"(a[3]), "r"(b[0]), "r"(b[1]));
}

// k-permute within an 8-chunk so frag pairs (k, k+4) are adjacent words (LDS.64)
__device__ __forceinline__ int kperm(int r) { return ((r & 3) << 1) | (r >> 2); }

// ================= Phase 1: G = x_rev @ Wx + bias (tf32 mma) =================
// C[16384, 4096], K=1024. Block tile 128x128, 8 warps (2Mx4N), warp tile 64x32.
#define P1_SA 40   // padded row stride (words) for conflict-free LDS.64
__global__ __launch_bounds__(256, 2) void gemm_xw_tc(const float* __restrict__ x,
                                                     const float* __restrict__ W,
                                                     const float* __restrict__ bias) {
    __shared__ uint32_t A_s[128 * P1_SA];   // [m][kperm]
    __shared__ uint32_t B_s[128 * P1_SA];   // [n][kperm]

    const int tid = threadIdx.x;
    const int wid = tid >> 5, lane = tid & 31;
    const int bn = blockIdx.x, bm = blockIdx.y;
    const int wm = wid >> 2, wn = wid & 3;   // warp grid 2x4
    const int l4 = lane & 3, g4 = lane >> 2;

    float acc[4][4][4];
#pragma unroll
    for (int i = 0; i < 4; ++i)
#pragma unroll
        for (int j = 0; j < 4; ++j)
#pragma unroll
            for (int e = 0; e < 4; ++e) acc[i][j][e] = 0.0f;

    for (int kc = 0; kc < D_; kc += 32) {
        // stage A (128x32) and B (32x128)
#pragma unroll
        for (int l = 0; l < 4; ++l) {
            int idx = tid + l * 256;
            // A: m = idx>>3, k-quad = (idx&7)*4
            int m = idx >> 3, k0 = (idx & 7) * 4;
            int R = bm * 128 + m;
            int tt = R >> 5, bb = R & 31;
            float4 av = *(const float4*)(x + ((size_t)bb * T_ + (size_t)(T_ - 1 - tt)) * D_ + kc + k0);
            {
                int k = k0;
                A_s[m * P1_SA + (k >> 3) * 8 + kperm(k & 7)] = f2tf32(av.x); k++;
                A_s[m * P1_SA + (k >> 3) * 8 + kperm(k & 7)] = f2tf32(av.y); k++;
                A_s[m * P1_SA + (k >> 3) * 8 + kperm(k & 7)] = f2tf32(av.z); k++;
                A_s[m * P1_SA + (k >> 3) * 8 + kperm(k & 7)] = f2tf32(av.w);
            }
            // B: k = idx>>5, n-quad = (idx&31)*4
            int kB = idx >> 5, n0 = (idx & 31) * 4;
            float4 bv = *(const float4*)(W + (size_t)(kc + kB) * ZN + bn * 128 + n0);
            int wpos = (kB >> 3) * 8 + kperm(kB & 7);
            B_s[(n0 + 0) * P1_SA + wpos] = f2tf32(bv.x);
            B_s[(n0 + 1) * P1_SA + wpos] = f2tf32(bv.y);
            B_s[(n0 + 2) * P1_SA + wpos] = f2tf32(bv.z);
            B_s[(n0 + 3) * P1_SA + wpos] = f2tf32(bv.w);
        }
        __syncthreads();

#pragma unroll
        for (int q = 0; q < 4; ++q) {
            uint32_t a[4][4], b[4][2];
#pragma unroll
            for (int mt = 0; mt < 4; ++mt) {
                int m = wm * 64 + mt * 16 + g4;
                uint2 lo = *(const uint2*)&A_s[m * P1_SA + q * 8 + 2 * l4];
                uint2 hi = *(const uint2*)&A_s[(m + 8) * P1_SA + q * 8 + 2 * l4];
                a[mt][0] = lo.x; a[mt][1] = hi.x; a[mt][2] = lo.y; a[mt][3] = hi.y;
            }
#pragma unroll
            for (int nt = 0; nt < 4; ++nt) {
                int n = wn * 32 + nt * 8 + g4;
                uint2 bv = *(const uint2*)&B_s[n * P1_SA + q * 8 + 2 * l4];
                b[nt][0] = bv.x; b[nt][1] = bv.y;
            }
#pragma unroll
            for (int mt = 0; mt < 4; ++mt)
#pragma unroll
                for (int nt = 0; nt < 4; ++nt)
                    mma_m16n8k8(acc[mt][nt], a[mt], b[nt]);
        }
        __syncthreads();
    }

    // epilogue: + bias, write g_G
#pragma unroll
    for (int mt = 0; mt < 4; ++mt) {
#pragma unroll
        for (int nt = 0; nt < 4; ++nt) {
            int R = bm * 128 + wm * 64 + mt * 16 + g4;
            int C = bn * 128 + wn * 32 + nt * 8 + 2 * l4;
            float2 bb2 = *(const float2*)(bias + C);
            float2 v0 = make_float2(acc[mt][nt][0] + bb2.x, acc[mt][nt][1] + bb2.y);
            float2 v1 = make_float2(acc[mt][nt][2] + bb2.x, acc[mt][nt][3] + bb2.y);
            *(float2*)&g_G[(size_t)R * ZN + C] = v0;
            *(float2*)&g_G[(size_t)(R + 8) * ZN + C] = v1;
        }
    }
}

// ================= Phase 2: persistent LSTM (tf32 mma) =================
// Block bn owns 8 hidden cols (32 z-cols). Weights slice persistent in SMEM
// (k-permuted, [c][1032]); h in global [k][b]; 8 warps split K by 128.
#define WS_S 1032                 // W_s row stride (words): 1024 + 8 pad
#define RED_S 36                  // red row stride
__global__ __launch_bounds__(256, 1) void lstm_seq_tc(const float* __restrict__ Wfull,
                                                      const float* __restrict__ out_unused,
                                                      float* __restrict__ out) {
    extern __shared__ uint32_t dynsmem[];
    uint32_t* W_s = dynsmem;                         // 32 * 1032 words
    float* red = (float*)(dynsmem + 32 * WS_S);      // 8 * 32 * 36 floats
    float* z_s = red + 8 * 32 * RED_S;               // 32 * 33 floats

    const float* Wh = Wfull + (size_t)D_ * ZN;
    const int tid = threadIdx.x;
    const int wid = tid >> 5, lane = tid & 31;
    const int l4 = lane & 3, g4 = lane >> 2;
    const int n0 = blockIdx.x * 8;
    const int pb = tid & 31;        // pointwise batch
    const int pn = tid >> 5;        // pointwise local hidden col

    // ---- load weight slice into SMEM (once), tf32-rounded, k-permuted ----
    for (int idx = tid; idx < 1024 * 32; idx += 256) {
        int k = idx >> 5, c = idx & 31;
        int col = (c >> 3) * H_ + n0 + (c & 7);
        float w = __ldg(Wh + (size_t)k * ZN + col);
        W_s[c * WS_S + (k >> 3) * 8 + kperm(k & 7)] = f2tf32(w);
    }
    __syncthreads();

    float c_reg;
    // ---- step 0: h = 0, z = G[0] ----
    {
        float iv = __ldg(&g_G[(size_t)pb * ZN + 0 * H_ + n0 + pn]);
        float jv = __ldg(&g_G[(size_t)pb * ZN + 1 * H_ + n0 + pn]);
        float fv = __ldg(&g_G[(size_t)pb * ZN + 2 * H_ + n0 + pn]);
        float ov = __ldg(&g_G[(size_t)pb * ZN + 3 * H_ + n0 + pn]);
        c_reg = sigf(iv) * tanhf(jv);
        float hv = sigf(ov) * tanhf(c_reg);
        out[(size_t)pb * (T_ * H_) + n0 + pn] = c_reg;
        __stcg(&g_h[1][(n0 + pn) * B_ + pb], __uint_as_float(f2tf32(hv)));
    }
    __threadfence();
    __syncthreads();
    if (tid == 0) atomicAdd(&g_bar, 1u);

    const int kbase = wid * 128;

    for (int t = 1; t < T_; ++t) {
        // ---- grid barrier: wait for all h of step t-1 ----
        if (tid == 0) {
            unsigned target = (unsigned)t * NBLK;
            while (*(volatile unsigned*)&g_bar < target) { }
            __threadfence();
        }
        __syncthreads();

        const float* hb = g_h[t & 1];
        float acc[2][4][4];
#pragma unroll
        for (int mt = 0; mt < 2; ++mt)
#pragma unroll
            for (int nt = 0; nt < 4; ++nt)
#pragma unroll
                for (int e = 0; e < 4; ++e) acc[mt][nt][e] = 0.0f;

#pragma unroll 4
        for (int q = 0; q < 16; ++q) {
            int k0 = kbase + q * 8;
            uint32_t a[2][4], b[4][2];
#pragma unroll
            for (int mt = 0; mt < 2; ++mt) {
                const float* hp = hb + (size_t)(k0 + l4) * B_ + g4 + mt * 16;
                a[mt][0] = __float_as_uint(__ldcg(hp));
                a[mt][1] = __float_as_uint(__ldcg(hp + 8));
                a[mt][2] = __float_as_uint(__ldcg(hp + 4 * B_));
                a[mt][3] = __float_as_uint(__ldcg(hp + 4 * B_ + 8));
            }
#pragma unroll
            for (int nt = 0; nt < 4; ++nt) {
                uint2 bv = *(const uint2*)&W_s[(nt * 8 + g4) * WS_S + k0 + 2 * l4];
                b[nt][0] = bv.x; b[nt][1] = bv.y;
            }
#pragma unroll
            for (int mt = 0; mt < 2; ++mt)
#pragma unroll
                for (int nt = 0; nt < 4; ++nt)
                    mma_m16n8k8(acc[mt][nt], a[mt], b[nt]);
        }

        // ---- store per-warp partials ----
#pragma unroll
        for (int mt = 0; mt < 2; ++mt) {
#pragma unroll
            for (int nt = 0; nt < 4; ++nt) {
                int row = mt * 16 + g4;
                int col = nt * 8 + 2 * l4;
                *(float2*)&red[wid * (32 * RED_S) + row * RED_S + col] =
                    make_float2(acc[mt][nt][0], acc[mt][nt][1]);
                *(float2*)&red[wid * (32 * RED_S) + (row + 8) * RED_S + col] =
                    make_float2(acc[mt][nt][2], acc[mt][nt][3]);
            }
        }
        __syncthreads();

        // ---- reduce 8 partials + G, into z_s ----
#pragma unroll
        for (int rep = 0; rep < 4; ++rep) {
            int o = tid + rep * 256;
            int b = o >> 5, c = o & 31;
            float s = __ldg(&g_G[((size_t)t * B_ + b) * ZN + (c >> 3) * H_ + n0 + (c & 7)]);
#pragma unroll
            for (int w = 0; w < 8; ++w) s += red[w * (32 * RED_S) + b * RED_S + c];
            z_s[b * 33 + c] = s;
        }
        __syncthreads();

        // ---- gates + output + next h ----
        {
            float iv = z_s[pb * 33 + pn];
            float jv = z_s[pb * 33 + 8 + pn];
            float fv = z_s[pb * 33 + 16 + pn];
            float ov = z_s[pb * 33 + 24 + pn];
            c_reg = sigf(fv + 1.0f) * c_reg + sigf(iv) * tanhf(jv);
            float hv = sigf(ov) * tanhf(c_reg);
            out[(size_t)pb * (T_ * H_) + (size_t)t * H_ + n0 + pn] = c_reg;
            __stcg(&g_h[(t + 1) & 1][(n0 + pn) * B_ + pb], __uint_as_float(f2tf32(hv)));
        }
        __threadfence();
        __syncthreads();
        if (tid == 0) atomicAdd(&g_bar, 1u);
    }

    // ---- reset counters for deterministic graph replay ----
    __syncthreads();
    if (tid == 0) {
        __threadfence();
        atomicAdd(&g_done, 1u);
        if (blockIdx.x == 0) {
            while (*(volatile unsigned*)&g_done < (unsigned)NBLK) { }
            g_bar = 0u;
            __threadfence();
            g_done = 0u;
            __threadfence();
        }
    }
}

// ---------------- launch ----------------
extern "C" void kernel_launch(void* const* d_in, const int* in_sizes, int n_in,
                              void* d_out, int out_size) {
    (void)in_sizes; (void)n_in; (void)out_size;
    const float* x    = (const float*)d_in[0];
    const float* kern = (const float*)d_in[2];
    const float* bias = (const float*)d_in[3];
    float* out = (float*)d_out;

    const int smem2 = (32 * WS_S + 8 * 32 * RED_S + 32 * 33) * 4;
    cudaFuncSetAttribute(lstm_seq_tc, cudaFuncAttributeMaxDynamicSharedMemorySize, smem2);

    dim3 g1(ZN / 128, (B_ * T_) / 128);   // (32, 128)
    gemm_xw_tc<<<g1, 256>>>(x, kern, bias);
    lstm_seq_tc<<<NBLK, 256, smem2>>>(kern, nullptr, out);
}

// round 3
// speedup vs baseline: 4.0900x; 1.4229x over previous
#include <cuda_runtime.h>
#include <cuda_bf16.h>
#include <math.h>
#include <stdint.h>

#define B_ 32
#define T_ 512
#define D_ 1024
#define H_ 1024
#define ZN 4096
#define NBLK 128

// ---------------- device scratch ----------------
__device__ float g_G[(size_t)T_ * B_ * ZN];       // 256MB: x@Wx + bias, row r = t*32+b (reversed time)
__device__ float g_Ap[(size_t)128 * 32 * 4096];   // 64MB: repacked x (tf32, kperm, tiled 128x32)
__device__ float g_Bp[(size_t)32 * 32 * 4096];    // 16MB: repacked Wx (tf32, kperm, tiled 128x32)
__device__ float g_h[2][H_ * B_];                 // double-buffered h, [k][b], tf32-rounded
__device__ unsigned g_bar = 0;
__device__ unsigned g_done = 0;

// ---------------- helpers ----------------
__device__ __forceinline__ float sigf(float x) { return 1.0f / (1.0f + __expf(-x)); }

__device__ __forceinline__ uint32_t f2tf32(float x) {
    uint32_t u;
    asm("cvt.rna.tf32.f32 %0, %1;" : "=r"(u) : "f"(x));
    return u;
}

__device__ __forceinline__ void mma_m16n8k8(float* c, const uint32_t* a, const uint32_t* b) {
    asm volatile(
        "mma.sync.aligned.m16n8k8.row.col.f32.tf32.tf32.f32 "
        "{%0,%1,%2,%3}, {%4,%5,%6,%7}, {%8,%9}, {%0,%1,%2,%3};"
        : "+f"(c[0]), "+f"(c[1]), "+f"(c[2]), "+f"(c[3])
        : "r"(a[0]), "r"(a[1]), "r"(a[2]), "r"(a[3]), "r"(b[0]), "r"(b[1]));
}

// k-permute within an 8-chunk so frag pairs (k, k+4) are adjacent words (LDS.64)
__device__ __forceinline__ int kperm(int r) { return ((r & 3) << 1) | (r >> 2); }

__device__ __forceinline__ void cpa16(float* dst, const float* src) {
    unsigned s = (unsigned)__cvta_generic_to_shared(dst);
    asm volatile("cp.async.cg.shared.global [%0], [%1], 16;" :: "r"(s), "l"(src));
}

// ================= Repack x: g_Ap[(mtile*32+kc)*4096 + r*32 + kperm] =================
__global__ __launch_bounds__(256) void repack_x(const float* __restrict__ x) {
    const int kc = blockIdx.x;      // 0..31
    const int mtile = blockIdx.y;   // 0..127
    const int tid = threadIdx.x;
    const int r = tid >> 1;                 // row in tile 0..127
    const int kk0 = (tid & 1) * 16;         // k-half

    const int R = mtile * 128 + r;
    const int tt = R >> 5, bb = R & 31;
    const float* src = x + ((size_t)bb * T_ + (size_t)(T_ - 1 - tt)) * D_ + kc * 32 + kk0;
    float* dst = g_Ap + ((size_t)(mtile * 32 + kc)) * 4096 + r * 32;

#pragma unroll
    for (int j = 0; j < 4; ++j) {
        float4 v = *(const float4*)(src + j * 4);
        int kk = kk0 + j * 4;
        dst[((kk + 0) >> 3) * 8 + kperm((kk + 0) & 7)] = __uint_as_float(f2tf32(v.x));
        dst[((kk + 1) >> 3) * 8 + kperm((kk + 1) & 7)] = __uint_as_float(f2tf32(v.y));
        dst[((kk + 2) >> 3) * 8 + kperm((kk + 2) & 7)] = __uint_as_float(f2tf32(v.z));
        dst[((kk + 3) >> 3) * 8 + kperm((kk + 3) & 7)] = __uint_as_float(f2tf32(v.w));
    }
}

// ================= Repack W (x-rows): g_Bp[(ntile*32+kc)*4096 + n*32 + kperm] =================
__global__ __launch_bounds__(256) void repack_w(const float* __restrict__ W) {
    const int kc = blockIdx.x;     // 0..31
    const int ntile = blockIdx.y;  // 0..31
    const int tid = threadIdx.x;
    const int kk = tid >> 3;               // 0..31 (k within chunk)
    const int nb = (tid & 7) * 16;         // n-block

    const int kpos = (kk >> 3) * 8 + kperm(kk & 7);
    const float* src = W + (size_t)(kc * 32 + kk) * ZN + ntile * 128 + nb;
    float* dst = g_Bp + ((size_t)(ntile * 32 + kc)) * 4096;

#pragma unroll
    for (int j = 0; j < 4; ++j) {
        float4 v = *(const float4*)(src + j * 4);
        int n = nb + j * 4;
        dst[(n + 0) * 32 + kpos] = __uint_as_float(f2tf32(v.x));
        dst[(n + 1) * 32 + kpos] = __uint_as_float(f2tf32(v.y));
        dst[(n + 2) * 32 + kpos] = __uint_as_float(f2tf32(v.z));
        dst[(n + 3) * 32 + kpos] = __uint_as_float(f2tf32(v.w));
    }
}

// ================= Phase 1: G = x_rev @ Wx + bias (tf32 mma, cp.async pipeline) ===========
#define ST 40   // smem row stride (words); 40 mod 32 == 8 -> conflict-free LDS.64 half-warps
__global__ __launch_bounds__(256, 2) void gemm_xw_tc(const float* __restrict__ bias) {
    extern __shared__ float smemf[];   // 2 stages x (A 128*ST + B 128*ST)

    const int tid = threadIdx.x;
    const int wid = tid >> 5, lane = tid & 31;
    const int bn = blockIdx.x, bm = blockIdx.y;
    const int wm = wid >> 2, wn = wid & 3;
    const int l4 = lane & 3, g4 = lane >> 2;

    // issue one K-chunk (32 k) into stage s
    auto issue = [&](int c, int s) {
        float* dstA = smemf + s * (2 * 128 * ST);
        float* dstB = dstA + 128 * ST;
        const float* srcA = g_Ap + ((size_t)(bm * 32 + c)) * 4096;
        const float* srcB = g_Bp + ((size_t)(bn * 32 + c)) * 4096;
#pragma unroll
        for (int j = 0; j < 4; ++j) {
            int G = tid + j * 256;
            int r = G >> 3, g = G & 7;
            cpa16(dstA + r * ST + g * 4, srcA + r * 32 + g * 4);
            cpa16(dstB + r * ST + g * 4, srcB + r * 32 + g * 4);
        }
        asm volatile("cp.async.commit_group;");
    };

    float acc[4][4][4];
#pragma unroll
    for (int i = 0; i < 4; ++i)
#pragma unroll
        for (int j = 0; j < 4; ++j)
#pragma unroll
            for (int e = 0; e < 4; ++e) acc[i][j][e] = 0.0f;

    issue(0, 0);
    issue(1, 1);

    for (int c = 0; c < 32; ++c) {
        asm volatile("cp.async.wait_group 1;");
        __syncthreads();
        const float* A_s = smemf + (c & 1) * (2 * 128 * ST);
        const float* B_s = A_s + 128 * ST;

#pragma unroll
        for (int q = 0; q < 4; ++q) {
            uint32_t a[4][4], b[4][2];
#pragma unroll
            for (int mt = 0; mt < 4; ++mt) {
                int m = wm * 64 + mt * 16 + g4;
                uint2 lo = *(const uint2*)&A_s[m * ST + q * 8 + 2 * l4];
                uint2 hi = *(const uint2*)&A_s[(m + 8) * ST + q * 8 + 2 * l4];
                a[mt][0] = lo.x; a[mt][1] = hi.x; a[mt][2] = lo.y; a[mt][3] = hi.y;
            }
#pragma unroll
            for (int nt = 0; nt < 4; ++nt) {
                int n = wn * 32 + nt * 8 + g4;
                uint2 bv = *(const uint2*)&B_s[n * ST + q * 8 + 2 * l4];
                b[nt][0] = bv.x; b[nt][1] = bv.y;
            }
#pragma unroll
            for (int mt = 0; mt < 4; ++mt)
#pragma unroll
                for (int nt = 0; nt < 4; ++nt)
                    mma_m16n8k8(acc[mt][nt], a[mt], b[nt]);
        }
        __syncthreads();
        if (c + 2 < 32) issue(c + 2, c & 1);
    }

    // epilogue: + bias, write g_G
#pragma unroll
    for (int mt = 0; mt < 4; ++mt) {
#pragma unroll
        for (int nt = 0; nt < 4; ++nt) {
            int R = bm * 128 + wm * 64 + mt * 16 + g4;
            int C = bn * 128 + wn * 32 + nt * 8 + 2 * l4;
            float2 bb2 = *(const float2*)(bias + C);
            float2 v0 = make_float2(acc[mt][nt][0] + bb2.x, acc[mt][nt][1] + bb2.y);
            float2 v1 = make_float2(acc[mt][nt][2] + bb2.x, acc[mt][nt][3] + bb2.y);
            *(float2*)&g_G[(size_t)R * ZN + C] = v0;
            *(float2*)&g_G[(size_t)(R + 8) * ZN + C] = v1;
        }
    }
}

// ================= Phase 2: persistent LSTM (tf32 mma) =================
#define WS_S 1032
#define RED_S 36
__global__ __launch_bounds__(256, 1) void lstm_seq_tc(const float* __restrict__ Wfull,
                                                      float* __restrict__ out) {
    extern __shared__ uint32_t dynsmem[];
    uint32_t* W_s = dynsmem;                         // 32 * 1032 words
    float* red = (float*)(dynsmem + 32 * WS_S);      // 8 * 32 * 36 floats
    float* z_s = red + 8 * 32 * RED_S;               // 32 * 33 floats

    const float* Wh = Wfull + (size_t)D_ * ZN;
    const int tid = threadIdx.x;
    const int wid = tid >> 5, lane = tid & 31;
    const int l4 = lane & 3, g4 = lane >> 2;
    const int n0 = blockIdx.x * 8;
    const int pb = tid >> 3;        // pointwise batch (coalesced out stores)
    const int pn = tid & 7;         // pointwise local hidden col

    // ---- load weight slice into SMEM (once), tf32-rounded, k-permuted ----
    for (int idx = tid; idx < 1024 * 32; idx += 256) {
        int k = idx >> 5, c = idx & 31;
        int col = (c >> 3) * H_ + n0 + (c & 7);
        float w = __ldg(Wh + (size_t)k * ZN + col);
        W_s[c * WS_S + (k >> 3) * 8 + kperm(k & 7)] = f2tf32(w);
    }
    __syncthreads();

    float c_reg;
    // ---- step 0: h = 0, z = G[0] ----
    {
        float iv = g_G[(size_t)pb * ZN + 0 * H_ + n0 + pn];
        float jv = g_G[(size_t)pb * ZN + 1 * H_ + n0 + pn];
        float fv = g_G[(size_t)pb * ZN + 2 * H_ + n0 + pn];
        float ov = g_G[(size_t)pb * ZN + 3 * H_ + n0 + pn];
        (void)fv;
        c_reg = sigf(iv) * tanhf(jv);
        float hv = sigf(ov) * tanhf(c_reg);
        __stcg(&g_h[1][(n0 + pn) * B_ + pb], __uint_as_float(f2tf32(hv)));
        __syncthreads();
        if (tid == 0) {
            unsigned one = 1u;
            asm volatile("red.release.gpu.add.u32 [%0], %1;" :: "l"(&g_bar), "r"(one) : "memory");
        }
        __stcs(&out[(size_t)pb * (T_ * H_) + n0 + pn], c_reg);
    }

    const int kbase = wid * 128;

    for (int t = 1; t < T_; ++t) {
        // ---- prefetch G[t] (independent of barrier) ----
        float gpre[4];
#pragma unroll
        for (int rep = 0; rep < 4; ++rep) {
            int o = tid + rep * 256;
            int bq = o >> 5, cq = o & 31;
            gpre[rep] = g_G[((size_t)t * B_ + bq) * ZN + (cq >> 3) * H_ + n0 + (cq & 7)];
        }

        // ---- grid barrier: wait for all h of step t-1 ----
        if (tid == 0) {
            unsigned target = (unsigned)t * NBLK;
            while (*(volatile unsigned*)&g_bar < target) { }
            __threadfence();
        }
        __syncthreads();

        const float* hb = g_h[t & 1];
        float acc[2][4][4];
#pragma unroll
        for (int mt = 0; mt < 2; ++mt)
#pragma unroll
            for (int nt = 0; nt < 4; ++nt)
#pragma unroll
                for (int e = 0; e < 4; ++e) acc[mt][nt][e] = 0.0f;

#pragma unroll 4
        for (int q = 0; q < 16; ++q) {
            int k0 = kbase + q * 8;
            uint32_t a[2][4], b[4][2];
#pragma unroll
            for (int mt = 0; mt < 2; ++mt) {
                const float* hp = hb + (size_t)(k0 + l4) * B_ + g4 + mt * 16;
                a[mt][0] = __float_as_uint(__ldcg(hp));
                a[mt][1] = __float_as_uint(__ldcg(hp + 8));
                a[mt][2] = __float_as_uint(__ldcg(hp + 4 * B_));
                a[mt][3] = __float_as_uint(__ldcg(hp + 4 * B_ + 8));
            }
#pragma unroll
            for (int nt = 0; nt < 4; ++nt) {
                uint2 bv = *(const uint2*)&W_s[(nt * 8 + g4) * WS_S + k0 + 2 * l4];
                b[nt][0] = bv.x; b[nt][1] = bv.y;
            }
#pragma unroll
            for (int mt = 0; mt < 2; ++mt)
#pragma unroll
                for (int nt = 0; nt < 4; ++nt)
                    mma_m16n8k8(acc[mt][nt], a[mt], b[nt]);
        }

        // ---- store per-warp partials ----
#pragma unroll
        for (int mt = 0; mt < 2; ++mt) {
#pragma unroll
            for (int nt = 0; nt < 4; ++nt) {
                int row = mt * 16 + g4;
                int col = nt * 8 + 2 * l4;
                *(float2*)&red[wid * (32 * RED_S) + row * RED_S + col] =
                    make_float2(acc[mt][nt][0], acc[mt][nt][1]);
                *(float2*)&red[wid * (32 * RED_S) + (row + 8) * RED_S + col] =
                    make_float2(acc[mt][nt][2], acc[mt][nt][3]);
            }
        }
        __syncthreads();

        // ---- reduce 8 partials + prefetched G, into z_s ----
#pragma unroll
        for (int rep = 0; rep < 4; ++rep) {
            int o = tid + rep * 256;
            int bq = o >> 5, cq = o & 31;
            float s = gpre[rep];
#pragma unroll
            for (int w = 0; w < 8; ++w) s += red[w * (32 * RED_S) + bq * RED_S + cq];
            z_s[bq * 33 + cq] = s;
        }
        __syncthreads();

        // ---- gates + h store + arrival + out store ----
        {
            float iv = z_s[pb * 33 + pn];
            float jv = z_s[pb * 33 + 8 + pn];
            float fv = z_s[pb * 33 + 16 + pn];
            float ov = z_s[pb * 33 + 24 + pn];
            c_reg = sigf(fv + 1.0f) * c_reg + sigf(iv) * tanhf(jv);
            float hv = sigf(ov) * tanhf(c_reg);
            __stcg(&g_h[(t + 1) & 1][(n0 + pn) * B_ + pb], __uint_as_float(f2tf32(hv)));
            __syncthreads();
            if (tid == 0) {
                unsigned one = 1u;
                asm volatile("red.release.gpu.add.u32 [%0], %1;" :: "l"(&g_bar), "r"(one) : "memory");
            }
            __stcs(&out[(size_t)pb * (T_ * H_) + (size_t)t * H_ + n0 + pn], c_reg);
        }
    }

    // ---- reset counters for deterministic graph replay ----
    __syncthreads();
    if (tid == 0) {
        __threadfence();
        atomicAdd(&g_done, 1u);
        if (blockIdx.x == 0) {
            while (*(volatile unsigned*)&g_done < (unsigned)NBLK) { }
            g_bar = 0u;
            __threadfence();
            g_done = 0u;
            __threadfence();
        }
    }
}

// ---------------- launch ----------------
extern "C" void kernel_launch(void* const* d_in, const int* in_sizes, int n_in,
                              void* d_out, int out_size) {
    (void)in_sizes; (void)n_in; (void)out_size;
    const float* x    = (const float*)d_in[0];
    const float* kern = (const float*)d_in[2];
    const float* bias = (const float*)d_in[3];
    float* out = (float*)d_out;

    const int smem1 = 2 * 2 * 128 * ST * 4;   // 81920 B
    const int smem2 = (32 * WS_S + 8 * 32 * RED_S + 32 * 33) * 4;
    cudaFuncSetAttribute(gemm_xw_tc, cudaFuncAttributeMaxDynamicSharedMemorySize, smem1);
    cudaFuncSetAttribute(lstm_seq_tc, cudaFuncAttributeMaxDynamicSharedMemorySize, smem2);

    repack_x<<<dim3(32, 128), 256>>>(x);
    repack_w<<<dim3(32, 32), 256>>>(kern);
    gemm_xw_tc<<<dim3(32, 128), 256, smem1>>>(bias);
    lstm_seq_tc<<<NBLK, 256, smem2>>>(kern, out);
}

// round 4
// speedup vs baseline: 5.6735x; 1.3871x over previous
#include <cuda_runtime.h>
#include <cuda_bf16.h>
#include <math.h>
#include <stdint.h>

#define B_ 32
#define T_ 512
#define D_ 1024
#define H_ 1024
#define ZN 4096
#define NBLK 128

// ---------------- device scratch ----------------
__device__ float g_G[(size_t)T_ * B_ * ZN];       // 256MB: x@Wx + bias, row r = t*32+b (reversed time)
__device__ float g_Ap[(size_t)128 * 32 * 4096];   // 64MB: repacked x (tf32, kperm, tiled 128x32)
__device__ float g_Bp[(size_t)32 * 32 * 4096];    // 16MB: repacked Wx (tf32, kperm, tiled 128x32)
__device__ float g_h[2][H_ * B_];                 // double-buffered h, packed [k>>3][b][kperm(k&7)]
__device__ unsigned g_flags[NBLK * 32];           // per-block progress flags, 128B apart
__device__ unsigned g_done = 0;

// ---------------- helpers ----------------
__device__ __forceinline__ float sigf(float x) { return 1.0f / (1.0f + __expf(-x)); }

__device__ __forceinline__ uint32_t f2tf32(float x) {
    uint32_t u;
    asm("cvt.rna.tf32.f32 %0, %1;" : "=r"(u) : "f"(x));
    return u;
}

__device__ __forceinline__ void mma_m16n8k8(float* c, const uint32_t* a, const uint32_t* b) {
    asm volatile(
        "mma.sync.aligned.m16n8k8.row.col.f32.tf32.tf32.f32 "
        "{%0,%1,%2,%3}, {%4,%5,%6,%7}, {%8,%9}, {%0,%1,%2,%3};"
        : "+f"(c[0]), "+f"(c[1]), "+f"(c[2]), "+f"(c[3])
        : "r"(a[0]), "r"(a[1]), "r"(a[2]), "r"(a[3]), "r"(b[0]), "r"(b[1]));
}

// k-permute within an 8-chunk so frag pairs (k, k+4) are adjacent words (LDS.64/LDG.64)
__device__ __forceinline__ int kperm(int r) { return ((r & 3) << 1) | (r >> 2); }

__device__ __forceinline__ void cpa16(float* dst, const float* src) {
    unsigned s = (unsigned)__cvta_generic_to_shared(dst);
    asm volatile("cp.async.cg.shared.global [%0], [%1], 16;" :: "r"(s), "l"(src));
}

__device__ __forceinline__ unsigned ld_acq(const unsigned* p) {
    unsigned v;
    asm volatile("ld.global.acquire.gpu.u32 %0, [%1];" : "=r"(v) : "l"(p) : "memory");
    return v;
}
__device__ __forceinline__ void st_rel(unsigned* p, unsigned v) {
    asm volatile("st.global.release.gpu.u32 [%0], %1;" :: "l"(p), "r"(v) : "memory");
}

// ================= Repack x: g_Ap[(mtile*32+kc)*4096 + r*32 + kperm] =================
__global__ __launch_bounds__(256) void repack_x(const float* __restrict__ x) {
    const int kc = blockIdx.x;      // 0..31
    const int mtile = blockIdx.y;   // 0..127
    const int tid = threadIdx.x;
    const int r = tid >> 1;
    const int kk0 = (tid & 1) * 16;

    const int R = mtile * 128 + r;
    const int tt = R >> 5, bb = R & 31;
    const float* src = x + ((size_t)bb * T_ + (size_t)(T_ - 1 - tt)) * D_ + kc * 32 + kk0;
    float* dst = g_Ap + ((size_t)(mtile * 32 + kc)) * 4096 + r * 32;

#pragma unroll
    for (int j = 0; j < 4; ++j) {
        float4 v = *(const float4*)(src + j * 4);
        int kk = kk0 + j * 4;
        dst[((kk + 0) >> 3) * 8 + kperm((kk + 0) & 7)] = __uint_as_float(f2tf32(v.x));
        dst[((kk + 1) >> 3) * 8 + kperm((kk + 1) & 7)] = __uint_as_float(f2tf32(v.y));
        dst[((kk + 2) >> 3) * 8 + kperm((kk + 2) & 7)] = __uint_as_float(f2tf32(v.z));
        dst[((kk + 3) >> 3) * 8 + kperm((kk + 3) & 7)] = __uint_as_float(f2tf32(v.w));
    }
}

// ================= Repack W (x-rows): g_Bp[(ntile*32+kc)*4096 + n*32 + kperm] =================
__global__ __launch_bounds__(256) void repack_w(const float* __restrict__ W) {
    const int kc = blockIdx.x;     // 0..31
    const int ntile = blockIdx.y;  // 0..31
    const int tid = threadIdx.x;
    const int kk = tid >> 3;
    const int nb = (tid & 7) * 16;

    const int kpos = (kk >> 3) * 8 + kperm(kk & 7);
    const float* src = W + (size_t)(kc * 32 + kk) * ZN + ntile * 128 + nb;
    float* dst = g_Bp + ((size_t)(ntile * 32 + kc)) * 4096;

#pragma unroll
    for (int j = 0; j < 4; ++j) {
        float4 v = *(const float4*)(src + j * 4);
        int n = nb + j * 4;
        dst[(n + 0) * 32 + kpos] = __uint_as_float(f2tf32(v.x));
        dst[(n + 1) * 32 + kpos] = __uint_as_float(f2tf32(v.y));
        dst[(n + 2) * 32 + kpos] = __uint_as_float(f2tf32(v.z));
        dst[(n + 3) * 32 + kpos] = __uint_as_float(f2tf32(v.w));
    }
}

// ================= Phase 1: G = x_rev @ Wx + bias (tf32 mma, cp.async pipeline) ===========
#define ST 40   // smem row stride (words); conflict-free LDS.64 half-warps
__global__ __launch_bounds__(256, 2) void gemm_xw_tc(const float* __restrict__ bias) {
    extern __shared__ float smemf[];   // 2 stages x (A 128*ST + B 128*ST)

    const int tid = threadIdx.x;
    const int wid = tid >> 5, lane = tid & 31;
    const int bn = blockIdx.x, bm = blockIdx.y;
    const int wm = wid >> 2, wn = wid & 3;
    const int l4 = lane & 3, g4 = lane >> 2;

    auto issue = [&](int c, int s) {
        float* dstA = smemf + s * (2 * 128 * ST);
        float* dstB = dstA + 128 * ST;
        const float* srcA = g_Ap + ((size_t)(bm * 32 + c)) * 4096;
        const float* srcB = g_Bp + ((size_t)(bn * 32 + c)) * 4096;
#pragma unroll
        for (int j = 0; j < 4; ++j) {
            int G = tid + j * 256;
            int r = G >> 3, g = G & 7;
            cpa16(dstA + r * ST + g * 4, srcA + r * 32 + g * 4);
            cpa16(dstB + r * ST + g * 4, srcB + r * 32 + g * 4);
        }
        asm volatile("cp.async.commit_group;");
    };

    float acc[4][4][4];
#pragma unroll
    for (int i = 0; i < 4; ++i)
#pragma unroll
        for (int j = 0; j < 4; ++j)
#pragma unroll
            for (int e = 0; e < 4; ++e) acc[i][j][e] = 0.0f;

    issue(0, 0);
    issue(1, 1);

    for (int c = 0; c < 32; ++c) {
        asm volatile("cp.async.wait_group 1;");
        __syncthreads();
        const float* A_s = smemf + (c & 1) * (2 * 128 * ST);
        const float* B_s = A_s + 128 * ST;

#pragma unroll
        for (int q = 0; q < 4; ++q) {
            uint32_t a[4][4], b[4][2];
#pragma unroll
            for (int mt = 0; mt < 4; ++mt) {
                int m = wm * 64 + mt * 16 + g4;
                uint2 lo = *(const uint2*)&A_s[m * ST + q * 8 + 2 * l4];
                uint2 hi = *(const uint2*)&A_s[(m + 8) * ST + q * 8 + 2 * l4];
                a[mt][0] = lo.x; a[mt][1] = hi.x; a[mt][2] = lo.y; a[mt][3] = hi.y;
            }
#pragma unroll
            for (int nt = 0; nt < 4; ++nt) {
                int n = wn * 32 + nt * 8 + g4;
                uint2 bv = *(const uint2*)&B_s[n * ST + q * 8 + 2 * l4];
                b[nt][0] = bv.x; b[nt][1] = bv.y;
            }
#pragma unroll
            for (int mt = 0; mt < 4; ++mt)
#pragma unroll
                for (int nt = 0; nt < 4; ++nt)
                    mma_m16n8k8(acc[mt][nt], a[mt], b[nt]);
        }
        __syncthreads();
        if (c + 2 < 32) issue(c + 2, c & 1);
    }

#pragma unroll
    for (int mt = 0; mt < 4; ++mt) {
#pragma unroll
        for (int nt = 0; nt < 4; ++nt) {
            int R = bm * 128 + wm * 64 + mt * 16 + g4;
            int C = bn * 128 + wn * 32 + nt * 8 + 2 * l4;
            float2 bb2 = *(const float2*)(bias + C);
            float2 v0 = make_float2(acc[mt][nt][0] + bb2.x, acc[mt][nt][1] + bb2.y);
            float2 v1 = make_float2(acc[mt][nt][2] + bb2.x, acc[mt][nt][3] + bb2.y);
            *(float2*)&g_G[(size_t)R * ZN + C] = v0;
            *(float2*)&g_G[(size_t)(R + 8) * ZN + C] = v1;
        }
    }
}

// ================= Phase 2: persistent LSTM (tf32 mma, 512 thr, flag barrier) =============
#define NT2 512
#define NW2 16
#define WS_S 1032
#define RED_S 36
__global__ __launch_bounds__(NT2, 1) void lstm_seq_tc(const float* __restrict__ Wfull,
                                                      float* __restrict__ out) {
    extern __shared__ uint32_t dynsmem[];
    uint32_t* W_s = dynsmem;                         // 32 * 1032 words
    float* red = (float*)(dynsmem + 32 * WS_S);      // 16 * 32 * 36 floats
    float* z_s = red + NW2 * 32 * RED_S;             // 32 * 33 floats

    const float* Wh = Wfull + (size_t)D_ * ZN;
    const int tid = threadIdx.x;
    const int wid = tid >> 5, lane = tid & 31;
    const int l4 = lane & 3, g4 = lane >> 2;
    const int bid = blockIdx.x;
    const int n0 = bid * 8;
    const int pb = (tid >> 3) & 31;  // pointwise batch (tid < 256 active)
    const int pn = tid & 7;          // pointwise local hidden col

    // ---- load weight slice into SMEM (once), tf32-rounded, k-permuted ----
    for (int idx = tid; idx < 1024 * 32; idx += NT2) {
        int k = idx >> 5, c = idx & 31;
        int col = (c >> 3) * H_ + n0 + (c & 7);
        float w = __ldg(Wh + (size_t)k * ZN + col);
        W_s[c * WS_S + (k >> 3) * 8 + kperm(k & 7)] = f2tf32(w);
    }
    __syncthreads();

    float c_reg = 0.0f;
    // ---- step 0: h = 0, z = G[0] ----
    if (tid < 256) {
        float iv = g_G[(size_t)pb * ZN + 0 * H_ + n0 + pn];
        float jv = g_G[(size_t)pb * ZN + 1 * H_ + n0 + pn];
        float ov = g_G[(size_t)pb * ZN + 3 * H_ + n0 + pn];
        c_reg = sigf(iv) * tanhf(jv);
        float hv = sigf(ov) * tanhf(c_reg);
        // packed h store: word = bid*256 + pb*8 + kperm(pn)
        __stcg(&g_h[1][bid * 256 + pb * 8 + kperm(pn)], __uint_as_float(f2tf32(hv)));
    }
    __syncthreads();
    if (tid == 0) { __threadfence(); st_rel(&g_flags[bid * 32], 1u); }
    if (tid < 256) __stcs(&out[(size_t)pb * (T_ * H_) + n0 + pn], c_reg);

    const int kb8 = wid * 8;   // (kbase >> 3) = wid*64/8

    for (int t = 1; t < T_; ++t) {
        // ---- prefetch G[t] (independent of barrier) ----
        float gpre[2];
#pragma unroll
        for (int rep = 0; rep < 2; ++rep) {
            int o = tid + rep * NT2;
            int bq = o >> 5, cq = o & 31;
            gpre[rep] = g_G[((size_t)t * B_ + bq) * ZN + (cq >> 3) * H_ + n0 + (cq & 7)];
        }

        // ---- distributed flag barrier: wait for all blocks at step t ----
        if (tid < NBLK) {
            while (ld_acq(&g_flags[tid * 32]) < (unsigned)t) { }
        }
        __syncthreads();

        const uint2* hb = (const uint2*)g_h[t & 1];
        float acc[2][4][4];
#pragma unroll
        for (int mt = 0; mt < 2; ++mt)
#pragma unroll
            for (int nt = 0; nt < 4; ++nt)
#pragma unroll
                for (int e = 0; e < 4; ++e) acc[mt][nt][e] = 0.0f;

#pragma unroll
        for (int q = 0; q < 8; ++q) {
            int k8 = kb8 + q;                 // k-chunk index (k0 = k8*8)
            uint32_t a[2][4], b[4][2];
#pragma unroll
            for (int mt = 0; mt < 2; ++mt) {
                const uint2* p = hb + k8 * 128 + (g4 + mt * 16) * 4 + l4;
                uint2 v0 = __ldcg(p);
                uint2 v1 = __ldcg(p + 32);    // rows +8 -> +64 words
                a[mt][0] = v0.x; a[mt][1] = v1.x; a[mt][2] = v0.y; a[mt][3] = v1.y;
            }
#pragma unroll
            for (int nt = 0; nt < 4; ++nt) {
                uint2 bv = *(const uint2*)&W_s[(nt * 8 + g4) * WS_S + k8 * 8 + 2 * l4];
                b[nt][0] = bv.x; b[nt][1] = bv.y;
            }
#pragma unroll
            for (int mt = 0; mt < 2; ++mt)
#pragma unroll
                for (int nt = 0; nt < 4; ++nt)
                    mma_m16n8k8(acc[mt][nt], a[mt], b[nt]);
        }

        // ---- store per-warp partials ----
#pragma unroll
        for (int mt = 0; mt < 2; ++mt) {
#pragma unroll
            for (int nt = 0; nt < 4; ++nt) {
                int row = mt * 16 + g4;
                int col = nt * 8 + 2 * l4;
                *(float2*)&red[wid * (32 * RED_S) + row * RED_S + col] =
                    make_float2(acc[mt][nt][0], acc[mt][nt][1]);
                *(float2*)&red[wid * (32 * RED_S) + (row + 8) * RED_S + col] =
                    make_float2(acc[mt][nt][2], acc[mt][nt][3]);
            }
        }
        __syncthreads();

        // ---- reduce 16 partials + prefetched G, into z_s ----
#pragma unroll
        for (int rep = 0; rep < 2; ++rep) {
            int o = tid + rep * NT2;
            int bq = o >> 5, cq = o & 31;
            float s = gpre[rep];
#pragma unroll
            for (int w = 0; w < NW2; ++w) s += red[w * (32 * RED_S) + bq * RED_S + cq];
            z_s[bq * 33 + cq] = s;
        }
        __syncthreads();

        // ---- gates + h store + arrival + out store ----
        if (tid < 256) {
            float iv = z_s[pb * 33 + pn];
            float jv = z_s[pb * 33 + 8 + pn];
            float fv = z_s[pb * 33 + 16 + pn];
            float ov = z_s[pb * 33 + 24 + pn];
            c_reg = sigf(fv + 1.0f) * c_reg + sigf(iv) * tanhf(jv);
            float hv = sigf(ov) * tanhf(c_reg);
            __stcg(&g_h[(t + 1) & 1][bid * 256 + pb * 8 + kperm(pn)],
                   __uint_as_float(f2tf32(hv)));
        }
        __syncthreads();
        if (tid == 0) { __threadfence(); st_rel(&g_flags[bid * 32], (unsigned)(t + 1)); }
        if (tid < 256) __stcs(&out[(size_t)pb * (T_ * H_) + (size_t)t * H_ + n0 + pn], c_reg);
    }

    // ---- reset flags for deterministic graph replay ----
    __syncthreads();
    if (tid == 0) atomicAdd(&g_done, 1u);
    if (bid == 0) {
        if (tid == 0) {
            while (*(volatile unsigned*)&g_done < (unsigned)NBLK) { }
        }
        __syncthreads();
        if (tid < NBLK) g_flags[tid * 32] = 0u;
        __syncthreads();
        if (tid == 0) { __threadfence(); g_done = 0u; }
    }
}

// ---------------- launch ----------------
extern "C" void kernel_launch(void* const* d_in, const int* in_sizes, int n_in,
                              void* d_out, int out_size) {
    (void)in_sizes; (void)n_in; (void)out_size;
    const float* x    = (const float*)d_in[0];
    const float* kern = (const float*)d_in[2];
    const float* bias = (const float*)d_in[3];
    float* out = (float*)d_out;

    const int smem1 = 2 * 2 * 128 * ST * 4;   // 81920 B
    const int smem2 = (32 * WS_S + NW2 * 32 * RED_S + 32 * 33) * 4;  // 210048 B
    cudaFuncSetAttribute(gemm_xw_tc, cudaFuncAttributeMaxDynamicSharedMemorySize, smem1);
    cudaFuncSetAttribute(lstm_seq_tc, cudaFuncAttributeMaxDynamicSharedMemorySize, smem2);

    repack_x<<<dim3(32, 128), 256>>>(x);
    repack_w<<<dim3(32, 32), 256>>>(kern);
    gemm_xw_tc<<<dim3(32, 128), 256, smem1>>>(bias);
    lstm_seq_tc<<<NBLK, NT2, smem2>>>(kern, out);
}

// round 5
// speedup vs baseline: 6.3943x; 1.1271x over previous
#include <cuda_runtime.h>
#include <cuda_bf16.h>
#include <math.h>
#include <stdint.h>

#define B_ 32
#define T_ 512
#define D_ 1024
#define H_ 1024
#define ZN 4096
#define NBLK 128

// ---------------- device scratch ----------------
__device__ float g_G[(size_t)T_ * B_ * ZN];       // 256MB: x@Wx + bias, row r = t*32+b (reversed time)
__device__ float g_Ap[(size_t)128 * 32 * 4096];   // 64MB: repacked x (tf32, kperm, tiled 128x32)
__device__ float g_Bp[(size_t)32 * 32 * 4096];    // 16MB: repacked Wx (tf32, kperm, tiled 128x32)
__device__ float g_h[2][H_ * B_];                 // double-buffered h, mma-fragment-packed (see h_word)
__device__ unsigned g_flags[NBLK * 32];           // per-block progress flags, 128B apart
__device__ unsigned g_done = 0;

// ---------------- helpers ----------------
__device__ __forceinline__ float sigf(float x) { return 1.0f / (1.0f + __expf(-x)); }

__device__ __forceinline__ uint32_t f2tf32(float x) {
    uint32_t u;
    asm("cvt.rna.tf32.f32 %0, %1;" : "=r"(u) : "f"(x));
    return u;
}

__device__ __forceinline__ void mma_m16n8k8(float* c, const uint32_t* a, const uint32_t* b) {
    asm volatile(
        "mma.sync.aligned.m16n8k8.row.col.f32.tf32.tf32.f32 "
        "{%0,%1,%2,%3}, {%4,%5,%6,%7}, {%8,%9}, {%0,%1,%2,%3};"
        : "+f"(c[0]), "+f"(c[1]), "+f"(c[2]), "+f"(c[3])
        : "r"(a[0]), "r"(a[1]), "r"(a[2]), "r"(a[3]), "r"(b[0]), "r"(b[1]));
}

// k-permute within an 8-chunk so frag pairs (k, k+4) are adjacent words (LDS.64)
__device__ __forceinline__ int kperm(int r) { return ((r & 3) << 1) | (r >> 2); }

// h packing: element (b, k) -> word index such that one LDG.128 per A-fragment.
// word(b,k) = (k>>3)*256 + (b>>4)*128 + (b&7)*16 + (k&3)*4 + ((k>>2)&1)*2 + ((b>>3)&1)
__device__ __forceinline__ int h_word(int b, int k) {
    return (k >> 3) * 256 + ((b >> 4) & 1) * 128 + (b & 7) * 16 +
           (k & 3) * 4 + ((k >> 2) & 1) * 2 + ((b >> 3) & 1);
}

__device__ __forceinline__ void cpa16(float* dst, const float* src) {
    unsigned s = (unsigned)__cvta_generic_to_shared(dst);
    asm volatile("cp.async.cg.shared.global [%0], [%1], 16;" :: "r"(s), "l"(src));
}

__device__ __forceinline__ unsigned ld_acq(const unsigned* p) {
    unsigned v;
    asm volatile("ld.global.acquire.gpu.u32 %0, [%1];" : "=r"(v) : "l"(p) : "memory");
    return v;
}
__device__ __forceinline__ void st_rel(unsigned* p, unsigned v) {
    asm volatile("st.global.release.gpu.u32 [%0], %1;" :: "l"(p), "r"(v) : "memory");
}

// ================= Repack x: g_Ap[(mtile*32+kc)*4096 + r*32 + kperm] =================
__global__ __launch_bounds__(256) void repack_x(const float* __restrict__ x) {
    const int kc = blockIdx.x;      // 0..31
    const int mtile = blockIdx.y;   // 0..127
    const int tid = threadIdx.x;
    const int r = tid >> 1;
    const int kk0 = (tid & 1) * 16;

    const int R = mtile * 128 + r;
    const int tt = R >> 5, bb = R & 31;
    const float* src = x + ((size_t)bb * T_ + (size_t)(T_ - 1 - tt)) * D_ + kc * 32 + kk0;
    float* dst = g_Ap + ((size_t)(mtile * 32 + kc)) * 4096 + r * 32;

#pragma unroll
    for (int j = 0; j < 4; ++j) {
        float4 v = *(const float4*)(src + j * 4);
        int kk = kk0 + j * 4;
        dst[((kk + 0) >> 3) * 8 + kperm((kk + 0) & 7)] = __uint_as_float(f2tf32(v.x));
        dst[((kk + 1) >> 3) * 8 + kperm((kk + 1) & 7)] = __uint_as_float(f2tf32(v.y));
        dst[((kk + 2) >> 3) * 8 + kperm((kk + 2) & 7)] = __uint_as_float(f2tf32(v.z));
        dst[((kk + 3) >> 3) * 8 + kperm((kk + 3) & 7)] = __uint_as_float(f2tf32(v.w));
    }
}

// ================= Repack W (x-rows): g_Bp[(ntile*32+kc)*4096 + n*32 + kperm] =================
__global__ __launch_bounds__(256) void repack_w(const float* __restrict__ W) {
    const int kc = blockIdx.x;     // 0..31
    const int ntile = blockIdx.y;  // 0..31
    const int tid = threadIdx.x;
    const int kk = tid >> 3;
    const int nb = (tid & 7) * 16;

    const int kpos = (kk >> 3) * 8 + kperm(kk & 7);
    const float* src = W + (size_t)(kc * 32 + kk) * ZN + ntile * 128 + nb;
    float* dst = g_Bp + ((size_t)(ntile * 32 + kc)) * 4096;

#pragma unroll
    for (int j = 0; j < 4; ++j) {
        float4 v = *(const float4*)(src + j * 4);
        int n = nb + j * 4;
        dst[(n + 0) * 32 + kpos] = __uint_as_float(f2tf32(v.x));
        dst[(n + 1) * 32 + kpos] = __uint_as_float(f2tf32(v.y));
        dst[(n + 2) * 32 + kpos] = __uint_as_float(f2tf32(v.z));
        dst[(n + 3) * 32 + kpos] = __uint_as_float(f2tf32(v.w));
    }
}

// ================= Phase 1: G = x_rev @ Wx + bias (tf32 mma, cp.async pipeline) ===========
#define ST 40   // smem row stride (words); conflict-free LDS.64 half-warps
__global__ __launch_bounds__(256, 2) void gemm_xw_tc(const float* __restrict__ bias) {
    extern __shared__ float smemf[];

    const int tid = threadIdx.x;
    const int wid = tid >> 5, lane = tid & 31;
    const int bn = blockIdx.x, bm = blockIdx.y;
    const int wm = wid >> 2, wn = wid & 3;
    const int l4 = lane & 3, g4 = lane >> 2;

    auto issue = [&](int c, int s) {
        float* dstA = smemf + s * (2 * 128 * ST);
        float* dstB = dstA + 128 * ST;
        const float* srcA = g_Ap + ((size_t)(bm * 32 + c)) * 4096;
        const float* srcB = g_Bp + ((size_t)(bn * 32 + c)) * 4096;
#pragma unroll
        for (int j = 0; j < 4; ++j) {
            int G = tid + j * 256;
            int r = G >> 3, g = G & 7;
            cpa16(dstA + r * ST + g * 4, srcA + r * 32 + g * 4);
            cpa16(dstB + r * ST + g * 4, srcB + r * 32 + g * 4);
        }
        asm volatile("cp.async.commit_group;");
    };

    float acc[4][4][4];
#pragma unroll
    for (int i = 0; i < 4; ++i)
#pragma unroll
        for (int j = 0; j < 4; ++j)
#pragma unroll
            for (int e = 0; e < 4; ++e) acc[i][j][e] = 0.0f;

    issue(0, 0);
    issue(1, 1);

    for (int c = 0; c < 32; ++c) {
        asm volatile("cp.async.wait_group 1;");
        __syncthreads();
        const float* A_s = smemf + (c & 1) * (2 * 128 * ST);
        const float* B_s = A_s + 128 * ST;

#pragma unroll
        for (int q = 0; q < 4; ++q) {
            uint32_t a[4][4], b[4][2];
#pragma unroll
            for (int mt = 0; mt < 4; ++mt) {
                int m = wm * 64 + mt * 16 + g4;
                uint2 lo = *(const uint2*)&A_s[m * ST + q * 8 + 2 * l4];
                uint2 hi = *(const uint2*)&A_s[(m + 8) * ST + q * 8 + 2 * l4];
                a[mt][0] = lo.x; a[mt][1] = hi.x; a[mt][2] = lo.y; a[mt][3] = hi.y;
            }
#pragma unroll
            for (int nt = 0; nt < 4; ++nt) {
                int n = wn * 32 + nt * 8 + g4;
                uint2 bv = *(const uint2*)&B_s[n * ST + q * 8 + 2 * l4];
                b[nt][0] = bv.x; b[nt][1] = bv.y;
            }
#pragma unroll
            for (int mt = 0; mt < 4; ++mt)
#pragma unroll
                for (int nt = 0; nt < 4; ++nt)
                    mma_m16n8k8(acc[mt][nt], a[mt], b[nt]);
        }
        __syncthreads();
        if (c + 2 < 32) issue(c + 2, c & 1);
    }

#pragma unroll
    for (int mt = 0; mt < 4; ++mt) {
#pragma unroll
        for (int nt = 0; nt < 4; ++nt) {
            int R = bm * 128 + wm * 64 + mt * 16 + g4;
            int C = bn * 128 + wn * 32 + nt * 8 + 2 * l4;
            float2 bb2 = *(const float2*)(bias + C);
            float2 v0 = make_float2(acc[mt][nt][0] + bb2.x, acc[mt][nt][1] + bb2.y);
            float2 v1 = make_float2(acc[mt][nt][2] + bb2.x, acc[mt][nt][3] + bb2.y);
            *(float2*)&g_G[(size_t)R * ZN + C] = v0;
            *(float2*)&g_G[(size_t)(R + 8) * ZN + C] = v1;
        }
    }
}

// ================= Phase 2: persistent LSTM (tf32 mma, 512 thr, flag barrier) =============
#define NT2 512
#define NW2 16
#define WS_S 1032
#define RED_S 40   // conflict-free reduce reads (8*pb + 8*g + pn covers banks once)
__global__ __launch_bounds__(NT2, 1) void lstm_seq_tc(const float* __restrict__ Wfull,
                                                      float* __restrict__ out) {
    extern __shared__ uint32_t dynsmem[];
    uint32_t* W_s = dynsmem;                         // 32 * 1032 words
    float* red = (float*)(dynsmem + 32 * WS_S);      // 16 * 32 * 40 floats

    const float* Wh = Wfull + (size_t)D_ * ZN;
    const int tid = threadIdx.x;
    const int wid = tid >> 5, lane = tid & 31;
    const int l4 = lane & 3, g4 = lane >> 2;
    const int bid = blockIdx.x;
    const int n0 = bid * 8;
    const int pb = (tid >> 3) & 31;
    const int pn = tid & 7;
    const bool active = tid < 256;
    const int hw = bid * 256 + ((pb >> 4) & 1) * 128 + (pb & 7) * 16 +
                   (pn & 3) * 4 + ((pn >> 2) & 1) * 2 + ((pb >> 3) & 1);

    // ---- load weight slice into SMEM (once), tf32-rounded, k-permuted ----
    for (int idx = tid; idx < 1024 * 32; idx += NT2) {
        int k = idx >> 5, c = idx & 31;
        int col = (c >> 3) * H_ + n0 + (c & 7);
        float w = __ldg(Wh + (size_t)k * ZN + col);
        W_s[c * WS_S + (k >> 3) * 8 + kperm(k & 7)] = f2tf32(w);
    }
    __syncthreads();

    float c_reg = 0.0f;
    float gq[4];
    // prefetch G[1] (pointwise mapping)
    if (active) {
#pragma unroll
        for (int g = 0; g < 4; ++g)
            gq[g] = g_G[(size_t)(32 + pb) * ZN + g * H_ + n0 + pn];
    }

    // ---- step 0: h = 0, z = G[0] ----
    if (active) {
        float iv = g_G[(size_t)pb * ZN + 0 * H_ + n0 + pn];
        float jv = g_G[(size_t)pb * ZN + 1 * H_ + n0 + pn];
        float ov = g_G[(size_t)pb * ZN + 3 * H_ + n0 + pn];
        c_reg = sigf(iv) * tanhf(jv);
        float hv = sigf(ov) * tanhf(c_reg);
        __stcg(&g_h[1][hw], __uint_as_float(f2tf32(hv)));
    }
    __syncthreads();
    if (tid == 0) st_rel(&g_flags[bid * 32], 1u);
    if (active) __stcs(&out[(size_t)pb * (T_ * H_) + n0 + pn], c_reg);

    const int kb8 = wid * 8;

    for (int t = 1; t < T_; ++t) {
        // ---- distributed flag barrier ----
        if (tid < NBLK) {
            while (ld_acq(&g_flags[tid * 32]) < (unsigned)t) { }
        }
        __syncthreads();

        // ---- prefetch G[t+1] (overlaps mma; consumed NEXT iteration) ----
        float gn[4];
        if (active) {
            int tn = (t + 1 < T_) ? t + 1 : T_ - 1;
#pragma unroll
            for (int g = 0; g < 4; ++g)
                gn[g] = g_G[((size_t)tn * B_ + pb) * ZN + g * H_ + n0 + pn];
        }

        const float4* hb = (const float4*)g_h[t & 1];
        float acc[2][4][4];
#pragma unroll
        for (int mt = 0; mt < 2; ++mt)
#pragma unroll
            for (int nt = 0; nt < 4; ++nt)
#pragma unroll
                for (int e = 0; e < 4; ++e) acc[mt][nt][e] = 0.0f;

#pragma unroll
        for (int q = 0; q < 8; ++q) {
            int k8 = kb8 + q;
            uint32_t a[2][4], b[4][2];
#pragma unroll
            for (int mt = 0; mt < 2; ++mt) {
                float4 v = __ldcg(&hb[k8 * 64 + mt * 32 + g4 * 4 + l4]);
                a[mt][0] = __float_as_uint(v.x); a[mt][1] = __float_as_uint(v.y);
                a[mt][2] = __float_as_uint(v.z); a[mt][3] = __float_as_uint(v.w);
            }
#pragma unroll
            for (int nt = 0; nt < 4; ++nt) {
                uint2 bv = *(const uint2*)&W_s[(nt * 8 + g4) * WS_S + k8 * 8 + 2 * l4];
                b[nt][0] = bv.x; b[nt][1] = bv.y;
            }
#pragma unroll
            for (int mt = 0; mt < 2; ++mt)
#pragma unroll
                for (int nt = 0; nt < 4; ++nt)
                    mma_m16n8k8(acc[mt][nt], a[mt], b[nt]);
        }

        // ---- store per-warp partials ----
#pragma unroll
        for (int mt = 0; mt < 2; ++mt) {
#pragma unroll
            for (int nt = 0; nt < 4; ++nt) {
                int row = mt * 16 + g4;
                int col = nt * 8 + 2 * l4;
                *(float2*)&red[wid * (32 * RED_S) + row * RED_S + col] =
                    make_float2(acc[mt][nt][0], acc[mt][nt][1]);
                *(float2*)&red[wid * (32 * RED_S) + (row + 8) * RED_S + col] =
                    make_float2(acc[mt][nt][2], acc[mt][nt][3]);
            }
        }
        __syncthreads();

        // ---- merged reduce + gates + h store ----
        if (active) {
            float z[4];
#pragma unroll
            for (int g = 0; g < 4; ++g) {
                float s = gq[g];
#pragma unroll
                for (int w = 0; w < NW2; ++w)
                    s += red[w * (32 * RED_S) + pb * RED_S + g * 8 + pn];
                z[g] = s;
            }
            c_reg = sigf(z[2] + 1.0f) * c_reg + sigf(z[0]) * tanhf(z[1]);
            float hv = sigf(z[3]) * tanhf(c_reg);
            __stcg(&g_h[(t + 1) & 1][hw], __uint_as_float(f2tf32(hv)));
        }
        __syncthreads();
        if (tid == 0) st_rel(&g_flags[bid * 32], (unsigned)(t + 1));
        if (active) __stcs(&out[(size_t)pb * (T_ * H_) + (size_t)t * H_ + n0 + pn], c_reg);

#pragma unroll
        for (int g = 0; g < 4; ++g) gq[g] = gn[g];
    }

    // ---- reset flags for deterministic graph replay ----
    __syncthreads();
    if (tid == 0) atomicAdd(&g_done, 1u);
    if (bid == 0) {
        if (tid == 0) {
            while (*(volatile unsigned*)&g_done < (unsigned)NBLK) { }
        }
        __syncthreads();
        if (tid < NBLK) g_flags[tid * 32] = 0u;
        __syncthreads();
        if (tid == 0) { __threadfence(); g_done = 0u; }
    }
}

// ---------------- launch ----------------
extern "C" void kernel_launch(void* const* d_in, const int* in_sizes, int n_in,
                              void* d_out, int out_size) {
    (void)in_sizes; (void)n_in; (void)out_size;
    const float* x    = (const float*)d_in[0];
    const float* kern = (const float*)d_in[2];
    const float* bias = (const float*)d_in[3];
    float* out = (float*)d_out;

    const int smem1 = 2 * 2 * 128 * ST * 4;   // 81920 B
    const int smem2 = (32 * WS_S + NW2 * 32 * RED_S) * 4;  // 214016 B
    cudaFuncSetAttribute(gemm_xw_tc, cudaFuncAttributeMaxDynamicSharedMemorySize, smem1);
    cudaFuncSetAttribute(lstm_seq_tc, cudaFuncAttributeMaxDynamicSharedMemorySize, smem2);

    repack_x<<<dim3(32, 128), 256>>>(x);
    repack_w<<<dim3(32, 32), 256>>>(kern);
    gemm_xw_tc<<<dim3(32, 128), 256, smem1>>>(bias);
    lstm_seq_tc<<<NBLK, NT2, smem2>>>(kern, out);
}

// round 7
// speedup vs baseline: 6.9496x; 1.0868x over previous
#include <cuda_runtime.h>
#include <cuda_bf16.h>
#include <math.h>
#include <stdint.h>

#define B_ 32
#define T_ 512
#define D_ 1024
#define H_ 1024
#define ZN 4096
#define NBLK 128

// ---------------- device scratch ----------------
__device__ float g_G[(size_t)T_ * B_ * ZN];       // 256MB: x@Wx + bias, row r = t*32+b (reversed time)
__device__ float g_Ap[(size_t)128 * 32 * 4096];   // 64MB: repacked x (tf32, kperm, tiled 128x32)
__device__ float g_Bp[(size_t)32 * 32 * 4096];    // 16MB: repacked Wx (tf32, kperm, tiled 128x32)
__device__ float g_h[2][H_ * B_];                 // double-buffered h, mma-fragment-packed
__device__ unsigned g_flags[NBLK * 32];           // per-block progress flags, 128B apart
__device__ unsigned g_done = 0;

// ---------------- helpers ----------------
__device__ __forceinline__ float sigf(float x) { return 1.0f / (1.0f + __expf(-x)); }

__device__ __forceinline__ uint32_t f2tf32(float x) {
    uint32_t u;
    asm("cvt.rna.tf32.f32 %0, %1;" : "=r"(u) : "f"(x));
    return u;
}

__device__ __forceinline__ void mma_m16n8k8(float* c, const uint32_t* a, uint32_t b0, uint32_t b1) {
    asm volatile(
        "mma.sync.aligned.m16n8k8.row.col.f32.tf32.tf32.f32 "
        "{%0,%1,%2,%3}, {%4,%5,%6,%7}, {%8,%9}, {%0,%1,%2,%3};"
        : "+f"(c[0]), "+f"(c[1]), "+f"(c[2]), "+f"(c[3])
        : "r"(a[0]), "r"(a[1]), "r"(a[2]), "r"(a[3]), "r"(b0), "r"(b1));
}

// k-permute within an 8-chunk so frag pairs (k, k+4) are adjacent words (LDS.64)
__device__ __forceinline__ int kperm(int r) { return ((r & 3) << 1) | (r >> 2); }

__device__ __forceinline__ void cpa16(float* dst, const float* src) {
    unsigned s = (unsigned)__cvta_generic_to_shared(dst);
    asm volatile("cp.async.cg.shared.global [%0], [%1], 16;" :: "r"(s), "l"(src));
}

__device__ __forceinline__ unsigned ld_acq(const unsigned* p) {
    unsigned v;
    asm volatile("ld.global.acquire.gpu.u32 %0, [%1];" : "=r"(v) : "l"(p) : "memory");
    return v;
}
__device__ __forceinline__ void st_rel(unsigned* p, unsigned v) {
    asm volatile("st.global.release.gpu.u32 [%0], %1;" :: "l"(p), "r"(v) : "memory");
}

// ================= Repack x: g_Ap[(mtile*32+kc)*4096 + r*32 + kperm] =================
__global__ __launch_bounds__(256) void repack_x(const float* __restrict__ x) {
    const int kc = blockIdx.x;      // 0..31
    const int mtile = blockIdx.y;   // 0..127
    const int tid = threadIdx.x;
    const int r = tid >> 1;
    const int kk0 = (tid & 1) * 16;

    const int R = mtile * 128 + r;
    const int tt = R >> 5, bb = R & 31;
    const float* src = x + ((size_t)bb * T_ + (size_t)(T_ - 1 - tt)) * D_ + kc * 32 + kk0;
    float* dst = g_Ap + ((size_t)(mtile * 32 + kc)) * 4096 + r * 32;

#pragma unroll
    for (int j = 0; j < 4; ++j) {
        float4 v = *(const float4*)(src + j * 4);
        int kk = kk0 + j * 4;
        dst[((kk + 0) >> 3) * 8 + kperm((kk + 0) & 7)] = __uint_as_float(f2tf32(v.x));
        dst[((kk + 1) >> 3) * 8 + kperm((kk + 1) & 7)] = __uint_as_float(f2tf32(v.y));
        dst[((kk + 2) >> 3) * 8 + kperm((kk + 2) & 7)] = __uint_as_float(f2tf32(v.z));
        dst[((kk + 3) >> 3) * 8 + kperm((kk + 3) & 7)] = __uint_as_float(f2tf32(v.w));
    }
}

// ================= Repack W (x-rows): g_Bp[(ntile*32+kc)*4096 + n*32 + kperm] =================
__global__ __launch_bounds__(256) void repack_w(const float* __restrict__ W) {
    const int kc = blockIdx.x;     // 0..31
    const int ntile = blockIdx.y;  // 0..31
    const int tid = threadIdx.x;
    const int kk = tid >> 3;
    const int nb = (tid & 7) * 16;

    const int kpos = (kk >> 3) * 8 + kperm(kk & 7);
    const float* src = W + (size_t)(kc * 32 + kk) * ZN + ntile * 128 + nb;
    float* dst = g_Bp + ((size_t)(ntile * 32 + kc)) * 4096;

#pragma unroll
    for (int j = 0; j < 4; ++j) {
        float4 v = *(const float4*)(src + j * 4);
        int n = nb + j * 4;
        dst[(n + 0) * 32 + kpos] = __uint_as_float(f2tf32(v.x));
        dst[(n + 1) * 32 + kpos] = __uint_as_float(f2tf32(v.y));
        dst[(n + 2) * 32 + kpos] = __uint_as_float(f2tf32(v.z));
        dst[(n + 3) * 32 + kpos] = __uint_as_float(f2tf32(v.w));
    }
}

// ================= Phase 1: G = x_rev @ Wx + bias (tf32 mma, cp.async pipeline) ===========
#define ST 40
__global__ __launch_bounds__(256, 2) void gemm_xw_tc(const float* __restrict__ bias) {
    extern __shared__ float smemf[];

    const int tid = threadIdx.x;
    const int wid = tid >> 5, lane = tid & 31;
    const int bn = blockIdx.x, bm = blockIdx.y;
    const int wm = wid >> 2, wn = wid & 3;
    const int l4 = lane & 3, g4 = lane >> 2;

    auto issue = [&](int c, int s) {
        float* dstA = smemf + s * (2 * 128 * ST);
        float* dstB = dstA + 128 * ST;
        const float* srcA = g_Ap + ((size_t)(bm * 32 + c)) * 4096;
        const float* srcB = g_Bp + ((size_t)(bn * 32 + c)) * 4096;
#pragma unroll
        for (int j = 0; j < 4; ++j) {
            int G = tid + j * 256;
            int r = G >> 3, g = G & 7;
            cpa16(dstA + r * ST + g * 4, srcA + r * 32 + g * 4);
            cpa16(dstB + r * ST + g * 4, srcB + r * 32 + g * 4);
        }
        asm volatile("cp.async.commit_group;");
    };

    float acc[4][4][4];
#pragma unroll
    for (int i = 0; i < 4; ++i)
#pragma unroll
        for (int j = 0; j < 4; ++j)
#pragma unroll
            for (int e = 0; e < 4; ++e) acc[i][j][e] = 0.0f;

    issue(0, 0);
    issue(1, 1);

    for (int c = 0; c < 32; ++c) {
        asm volatile("cp.async.wait_group 1;");
        __syncthreads();
        const float* A_s = smemf + (c & 1) * (2 * 128 * ST);
        const float* B_s = A_s + 128 * ST;

#pragma unroll
        for (int q = 0; q < 4; ++q) {
            uint32_t a[4][4], b[4][2];
#pragma unroll
            for (int mt = 0; mt < 4; ++mt) {
                int m = wm * 64 + mt * 16 + g4;
                uint2 lo = *(const uint2*)&A_s[m * ST + q * 8 + 2 * l4];
                uint2 hi = *(const uint2*)&A_s[(m + 8) * ST + q * 8 + 2 * l4];
                a[mt][0] = lo.x; a[mt][1] = hi.x; a[mt][2] = lo.y; a[mt][3] = hi.y;
            }
#pragma unroll
            for (int nt = 0; nt < 4; ++nt) {
                int n = wn * 32 + nt * 8 + g4;
                uint2 bv = *(const uint2*)&B_s[n * ST + q * 8 + 2 * l4];
                b[nt][0] = bv.x; b[nt][1] = bv.y;
            }
#pragma unroll
            for (int mt = 0; mt < 4; ++mt)
#pragma unroll
                for (int nt = 0; nt < 4; ++nt)
                    mma_m16n8k8(acc[mt][nt], a[mt], b[nt][0], b[nt][1]);
        }
        __syncthreads();
        if (c + 2 < 32) issue(c + 2, c & 1);
    }

#pragma unroll
    for (int mt = 0; mt < 4; ++mt) {
#pragma unroll
        for (int nt = 0; nt < 4; ++nt) {
            int R = bm * 128 + wm * 64 + mt * 16 + g4;
            int C = bn * 128 + wn * 32 + nt * 8 + 2 * l4;
            float2 bb2 = *(const float2*)(bias + C);
            float2 v0 = make_float2(acc[mt][nt][0] + bb2.x, acc[mt][nt][1] + bb2.y);
            float2 v1 = make_float2(acc[mt][nt][2] + bb2.x, acc[mt][nt][3] + bb2.y);
            *(float2*)&g_G[(size_t)R * ZN + C] = v0;
            *(float2*)&g_G[(size_t)(R + 8) * ZN + C] = v1;
        }
    }
}

// ================= Phase 2: persistent LSTM (tf32 mma, per-warp producer polling) =========
// 16 warps = 8 K-groups x 2 N-halves. Warp (kgrp,nh): K rows [kgrp*128, +128),
// z cols [nh*16, +16). Each warp polls ONLY its 16 producer blocks' flags.
#define NT2 512
#define RED_S 40
__global__ __launch_bounds__(NT2, 1) void lstm_seq_tc(const float* __restrict__ Wfull,
                                                      float* __restrict__ out) {
    extern __shared__ uint32_t dynsmem[];
    uint32_t* W_s = dynsmem;                         // 16 slabs * 2048 words = 32768 words
    float* red = (float*)(dynsmem + 16 * 2048);      // 8 * 32 * 40 floats

    const float* Wh = Wfull + (size_t)D_ * ZN;
    const int tid = threadIdx.x;
    const int wid = tid >> 5, lane = tid & 31;
    const int l4 = lane & 3, g4 = lane >> 2;
    const int bid = blockIdx.x;
    const int n0 = bid * 8;
    const int pb = (tid >> 3) & 31;
    const int pn = tid & 7;
    const bool active = tid < 256;
    const int kgrp = wid >> 1, nh = wid & 1;
    const int hw = bid * 256 + ((pb >> 4) & 1) * 128 + (pb & 7) * 16 +
                   (pn & 3) * 4 + ((pn >> 2) & 1) * 2 + ((pb >> 3) & 1);

    // ---- load weight slice into SMEM, warp-centric pack: one uint4 = both n-tile b-frags ----
    // dst word: slab(=kgrp*2+nh)*2048 + q*128 + (g4c*4 + l4k)*4 + nt*2 + jk
    for (int idx = tid; idx < 1024 * 32; idx += NT2) {
        int k = idx >> 5, c = idx & 31;
        float w = __ldg(Wh + (size_t)k * ZN + (c >> 3) * H_ + n0 + (c & 7));
        int kg = k >> 7, q = (k >> 3) & 15, l4k = k & 3, jk = (k >> 2) & 1;
        int nhh = (c >> 4) & 1, nt = (c >> 3) & 1, g4c = c & 7;
        W_s[(kg * 2 + nhh) * 2048 + q * 128 + (g4c * 4 + l4k) * 4 + nt * 2 + jk] = f2tf32(w);
    }
    __syncthreads();

    float c_reg = 0.0f;
    float gq[4];
    if (active) {
#pragma unroll
        for (int g = 0; g < 4; ++g)
            gq[g] = g_G[(size_t)(32 + pb) * ZN + g * H_ + n0 + pn];
    }

    // ---- step 0: h = 0, z = G[0] ----
    if (active) {
        float iv = g_G[(size_t)pb * ZN + 0 * H_ + n0 + pn];
        float jv = g_G[(size_t)pb * ZN + 1 * H_ + n0 + pn];
        float ov = g_G[(size_t)pb * ZN + 3 * H_ + n0 + pn];
        c_reg = sigf(iv) * tanhf(jv);
        float hv = sigf(ov) * tanhf(c_reg);
        __stcg(&g_h[1][hw], __uint_as_float(f2tf32(hv)));
    }
    __syncthreads();
    if (tid == 0) st_rel(&g_flags[bid * 32], 1u);
    if (active) __stcs(&out[(size_t)pb * (T_ * H_) + n0 + pn], c_reg);

    const uint4* Wq = (const uint4*)W_s + (size_t)wid * 512;

    for (int t = 1; t < T_; ++t) {
        // ---- prefetch G[t+1] (flag-independent; consumed next iteration) ----
        float gn[4];
        if (active) {
            int tn = (t + 1 < T_) ? t + 1 : T_ - 1;
#pragma unroll
            for (int g = 0; g < 4; ++g)
                gn[g] = g_G[((size_t)tn * B_ + pb) * ZN + g * H_ + n0 + pn];
        }

        // ---- per-warp poll: only this warp's 16 producer blocks ----
        if (lane < 16) {
            const unsigned* fp = &g_flags[(kgrp * 16 + lane) * 32];
            while (ld_acq(fp) < (unsigned)t) { }
        }
        __syncwarp();

        const float4* hb = (const float4*)g_h[t & 1];
        float acc[2][2][4];
#pragma unroll
        for (int mt = 0; mt < 2; ++mt)
#pragma unroll
            for (int nt = 0; nt < 2; ++nt)
#pragma unroll
                for (int e = 0; e < 4; ++e) acc[mt][nt][e] = 0.0f;

#pragma unroll
        for (int q = 0; q < 16; ++q) {
            int k8 = kgrp * 16 + q;
            uint4 bv = Wq[q * 32 + lane];   // LDS.128: both n-tile fragments
            uint32_t a[2][4];
#pragma unroll
            for (int mt = 0; mt < 2; ++mt) {
                float4 v = __ldcg(&hb[k8 * 64 + mt * 32 + g4 * 4 + l4]);
                a[mt][0] = __float_as_uint(v.x); a[mt][1] = __float_as_uint(v.y);
                a[mt][2] = __float_as_uint(v.z); a[mt][3] = __float_as_uint(v.w);
            }
#pragma unroll
            for (int mt = 0; mt < 2; ++mt) {
                mma_m16n8k8(acc[mt][0], a[mt], bv.x, bv.y);
                mma_m16n8k8(acc[mt][1], a[mt], bv.z, bv.w);
            }
        }

        // ---- store per-kgrp partials (two nh warps write disjoint cols) ----
#pragma unroll
        for (int mt = 0; mt < 2; ++mt) {
#pragma unroll
            for (int nt = 0; nt < 2; ++nt) {
                int row = mt * 16 + g4;
                int col = nh * 16 + nt * 8 + 2 * l4;
                *(float2*)&red[kgrp * (32 * RED_S) + row * RED_S + col] =
                    make_float2(acc[mt][nt][0], acc[mt][nt][1]);
                *(float2*)&red[kgrp * (32 * RED_S) + (row + 8) * RED_S + col] =
                    make_float2(acc[mt][nt][2], acc[mt][nt][3]);
            }
        }
        __syncthreads();

        // ---- merged reduce (8 partials) + gates + h store ----
        if (active) {
            float z[4];
#pragma unroll
            for (int g = 0; g < 4; ++g) {
                float s = gq[g];
#pragma unroll
                for (int kg = 0; kg < 8; ++kg)
                    s += red[kg * (32 * RED_S) + pb * RED_S + g * 8 + pn];
                z[g] = s;
            }
            c_reg = sigf(z[2] + 1.0f) * c_reg + sigf(z[0]) * tanhf(z[1]);
            float hv = sigf(z[3]) * tanhf(c_reg);
            __stcg(&g_h[(t + 1) & 1][hw], __uint_as_float(f2tf32(hv)));
        }
        __syncthreads();
        if (tid == 0) st_rel(&g_flags[bid * 32], (unsigned)(t + 1));
        if (active) __stcs(&out[(size_t)pb * (T_ * H_) + (size_t)t * H_ + n0 + pn], c_reg);

#pragma unroll
        for (int g = 0; g < 4; ++g) gq[g] = gn[g];
    }

    // ---- reset flags for deterministic graph replay ----
    __syncthreads();
    if (tid == 0) atomicAdd(&g_done, 1u);
    if (bid == 0) {
        if (tid == 0) {
            while (*(volatile unsigned*)&g_done < (unsigned)NBLK) { }
        }
        __syncthreads();
        if (tid < NBLK) g_flags[tid * 32] = 0u;
        __syncthreads();
        if (tid == 0) { __threadfence(); g_done = 0u; }
    }
}

// ---------------- launch ----------------
extern "C" void kernel_launch(void* const* d_in, const int* in_sizes, int n_in,
                              void* d_out, int out_size) {
    (void)in_sizes; (void)n_in; (void)out_size;
    const float* x    = (const float*)d_in[0];
    const float* kern = (const float*)d_in[2];
    const float* bias = (const float*)d_in[3];
    float* out = (float*)d_out;

    const int smem1 = 2 * 2 * 128 * ST * 4;                 // 81920 B
    const int smem2 = (16 * 2048 + 8 * 32 * RED_S) * 4;     // 172032 B
    cudaFuncSetAttribute(gemm_xw_tc, cudaFuncAttributeMaxDynamicSharedMemorySize, smem1);
    cudaFuncSetAttribute(lstm_seq_tc, cudaFuncAttributeMaxDynamicSharedMemorySize, smem2);

    repack_x<<<dim3(32, 128), 256>>>(x);
    repack_w<<<dim3(32, 32), 256>>>(kern);
    gemm_xw_tc<<<dim3(32, 128), 256, smem1>>>(bias);
    lstm_seq_tc<<<NBLK, NT2, smem2>>>(kern, out);
}